// round 9
// baseline (speedup 1.0000x reference)
#include <cuda_runtime.h>
#include <cuda_pipeline.h>

// Problem constants (fixed by the dataset instance)
#define W_ 256
#define PLANE 65536
#define THREADS 512
// Each block: TWO adjacent 16-patch tiles (64c x 4r x 64w each).
// Tile A: register-resident (LDG). Tile B: cp.async-staged to smem,
// issued during A's compute chain so DRAM stays busy.

__device__ __forceinline__ float sigm(float x) {
    return 1.0f / (1.0f + __expf(-x));
}

extern __shared__ float stage[];         // 16384 floats = 64 KB (tile B)

__global__ __launch_bounds__(THREADS, 2)
void ciam_bg_kernel(const float* __restrict__ x,
                    const float* __restrict__ fc_w,
                    const float* __restrict__ fc_b,
                    const float* __restrict__ c1w,
                    const float* __restrict__ c1b,
                    const float* __restrict__ c2w,
                    const float* __restrict__ c2b,
                    float* __restrict__ out)
{
    // ---- block / thread decomposition ----
    const int blk = blockIdx.x;          // 0..1023
    const int pw2 = blk & 1;             // tile pair along W: pwgA=2*pw2, pwgB=+1
    const int ph  = (blk >> 1) & 63;     // patch row
    const int b   = blk >> 7;            // batch

    const int t  = threadIdx.x;
    const int p  = t & 15;               // patch
    const int r  = (t >> 4) & 3;         // row within patch
    const int cb = t >> 6;               // channel base 0..7 (c = cb + 8k)
    const int rp = t & 63;               // (r, patch)

    // ---- static shared (~44.6 KB) ----
    __shared__ float wS[64 * 68];        // fc_w rows, stride 68
    __shared__ float fcbS[64];
    __shared__ float mxT[1024];          // channel maxes [c][p]
    __shared__ float msm[1024];          // channel attention m[c][p]
    __shared__ float g1s[256];           // g1[(r,p)*4 + px]
    __shared__ float p2s[256], p2m[256]; // g2 partials [warp][p]
    __shared__ float g2s[16];
    __shared__ float uni[4160];          // pm[4][1040] / gsum+gmax

    // ---- scalar weights ----
    const float c1w0 = __ldg(c1w), c1w1 = __ldg(c1w + 1), c1b0 = __ldg(c1b);
    const float c2w0 = __ldg(c2w), c2w1 = __ldg(c2w + 1), c2b0 = __ldg(c2b);

    const size_t plane = PLANE;
    const float* xb = x + (size_t)b * 64 * plane;
    float* ob = out + (size_t)b * 64 * plane;
    const int rbA = (ph * 4 + r) * W_ + (pw2 * 2 + 0) * 64 + p * 4;
    const int rbB = (ph * 4 + r) * W_ + (pw2 * 2 + 1) * 64 + p * 4;

    // ---- tile A: LDG into registers (burst) ----
    float4 v[8];
    #pragma unroll
    for (int k = 0; k < 8; k++)
        v[k] = *(const float4*)(xb + (size_t)(cb + 8 * k) * plane + rbA);

    // ---- stage fc_w (stride 68) / fc_b ----
    #pragma unroll
    for (int i = 0; i < 2; i++) {
        const int j  = t + 512 * i;      // float4 chunk 0..1023
        const int c  = j >> 4;
        const int k4 = j & 15;
        *(float4*)(wS + c * 68 + k4 * 4) = *(const float4*)(fc_w + c * 64 + k4 * 4);
    }
    if (t < 64) fcbS[t] = fc_b[t];

    // ---- A: per-(c,r,p) row max -> pm ----
    float* pm = uni;                     // [r][c*16+p], row stride 1040
    #pragma unroll
    for (int k = 0; k < 8; k++) {
        float4 a = v[k];
        pm[r * 1040 + (cb + 8 * k) * 16 + p] =
            fmaxf(fmaxf(a.x, a.y), fmaxf(a.z, a.w));
    }

    // ---- issue tile B cp.async NOW: streams during A's compute chain ----
    {
        const float* srcB = xb + (size_t)(ph * 4) * W_ + (pw2 * 2 + 1) * 64;
        #pragma unroll
        for (int i = 0; i < 8; i++) {
            const int j   = t + 512 * i;  // 0..4095 16B chunks
            const int c   = j >> 6;
            const int rr  = (j >> 4) & 3;
            const int w16 = j & 15;
            __pipeline_memcpy_async(stage + c * 256 + rr * 64 + w16 * 4,
                                    srcB + (size_t)c * plane + rr * W_ + w16 * 4, 16);
        }
        __pipeline_commit();
    }
    __syncthreads();

    // ---- chain: from r-reduce through store (shared by both tiles) ----
    auto rest = [&](float4* vv, int rowbase) {
        // reduce over r -> mxT (float4 form, 256 threads)
        if (t < 256) {
            const int id4 = t * 4;       // 0..1020
            float4 a0 = *(const float4*)(pm + id4);
            float4 a1 = *(const float4*)(pm + 1040 + id4);
            float4 a2 = *(const float4*)(pm + 2080 + id4);
            float4 a3 = *(const float4*)(pm + 3120 + id4);
            float4 mr;
            mr.x = fmaxf(fmaxf(a0.x, a1.x), fmaxf(a2.x, a3.x));
            mr.y = fmaxf(fmaxf(a0.y, a1.y), fmaxf(a2.y, a3.y));
            mr.z = fmaxf(fmaxf(a0.z, a1.z), fmaxf(a2.z, a3.z));
            mr.w = fmaxf(fmaxf(a0.w, a1.w), fmaxf(a2.w, a3.w));
            *(float4*)(mxT + id4) = mr;
        }
        __syncthreads();

        // matvec: 4 outputs/thread, float4 reads
        if (t < 256) {
            const int c  = t >> 2;
            const int pq = (t & 3) * 4;
            float4 acc = make_float4(0.f, 0.f, 0.f, 0.f);
            #pragma unroll
            for (int kc = 0; kc < 16; kc++) {
                const float4 w4 = *(const float4*)(wS + c * 68 + kc * 4);
                const float4 m0 = *(const float4*)(mxT + (kc * 4 + 0) * 16 + pq);
                const float4 m1 = *(const float4*)(mxT + (kc * 4 + 1) * 16 + pq);
                acc.x += w4.x * m0.x + w4.y * m1.x;
                acc.y += w4.x * m0.y + w4.y * m1.y;
                acc.z += w4.x * m0.z + w4.y * m1.z;
                acc.w += w4.x * m0.w + w4.y * m1.w;
                const float4 m2 = *(const float4*)(mxT + (kc * 4 + 2) * 16 + pq);
                const float4 m3 = *(const float4*)(mxT + (kc * 4 + 3) * 16 + pq);
                acc.x += w4.z * m2.x + w4.w * m3.x;
                acc.y += w4.z * m2.y + w4.w * m3.y;
                acc.z += w4.z * m2.z + w4.w * m3.z;
                acc.w += w4.z * m2.w + w4.w * m3.w;
            }
            const float bc = fcbS[c];
            float4 mres;
            mres.x = sigm(acc.x + bc);
            mres.y = sigm(acc.y + bc);
            mres.z = sigm(acc.z + bc);
            mres.w = sigm(acc.w + bc);
            *(float4*)(msm + c * 16 + pq) = mres;
        }
        __syncthreads();

        // apply channel attention; g1 partials over this thread's 8 channels
        float4 ps  = make_float4(0.f, 0.f, 0.f, 0.f);
        float4 pmx = make_float4(-3.4e38f, -3.4e38f, -3.4e38f, -3.4e38f);
        #pragma unroll
        for (int k = 0; k < 8; k++) {
            const float m = msm[(cb + 8 * k) * 16 + p];
            vv[k].x *= m; vv[k].y *= m; vv[k].z *= m; vv[k].w *= m;
            ps.x += vv[k].x; ps.y += vv[k].y; ps.z += vv[k].z; ps.w += vv[k].w;
            pmx.x = fmaxf(pmx.x, vv[k].x); pmx.y = fmaxf(pmx.y, vv[k].y);
            pmx.z = fmaxf(pmx.z, vv[k].z); pmx.w = fmaxf(pmx.w, vv[k].w);
        }
        float* gsum = uni;               // 2048 floats
        float* gmax = uni + 2048;
        *(float4*)(gsum + cb * 256 + rp * 4) = ps;
        *(float4*)(gmax + cb * 256 + rp * 4) = pmx;
        __syncthreads();

        // g1 per (patch, pixel)
        if (t < 256) {
            float s = 0.f, mx = -3.4e38f;
            #pragma unroll
            for (int g = 0; g < 8; g++) {
                s  += gsum[g * 256 + t];
                mx  = fmaxf(mx, gmax[g * 256 + t]);
            }
            g1s[t] = sigm(c1w0 * (s * (1.0f / 64.0f)) + c1w1 * mx + c1b0);
        }
        __syncthreads();

        // apply g1; g2 partials
        const float4 g1v = *(const float4*)(g1s + rp * 4);
        float s2 = 0.f, m2 = -3.4e38f;
        #pragma unroll
        for (int k = 0; k < 8; k++) {
            vv[k].x *= g1v.x; vv[k].y *= g1v.y; vv[k].z *= g1v.z; vv[k].w *= g1v.w;
            s2 += vv[k].x + vv[k].y + vv[k].z + vv[k].w;
            m2 = fmaxf(m2, fmaxf(fmaxf(vv[k].x, vv[k].y), fmaxf(vv[k].z, vv[k].w)));
        }
        s2 += __shfl_xor_sync(0xffffffffu, s2, 16);
        m2 = fmaxf(m2, __shfl_xor_sync(0xffffffffu, m2, 16));
        if ((t & 16) == 0)
            { p2s[(t >> 5) * 16 + p] = s2; p2m[(t >> 5) * 16 + p] = m2; }
        __syncthreads();
        if (t < 16) {
            float s = 0.f, mx = -3.4e38f;
            #pragma unroll
            for (int g = 0; g < 16; g++) {
                s += p2s[g * 16 + t];
                mx = fmaxf(mx, p2m[g * 16 + t]);
            }
            g2s[t] = sigm(c2w0 * (s * (1.0f / 1024.0f)) + c2w1 * mx + c2b0);
        }
        __syncthreads();
        const float g2 = g2s[p];

        // apply g2 and store
        #pragma unroll
        for (int k = 0; k < 8; k++) {
            float4 a = vv[k];
            a.x *= g2; a.y *= g2; a.z *= g2; a.w *= g2;
            *(float4*)(ob + (size_t)(cb + 8 * k) * plane + rowbase) = a;
        }
    };

    // ---- tile A chain (B streams in background) ----
    rest(v, rbA);

    // ---- switch to tile B: wait for cp.async, reload v from smem ----
    __pipeline_wait_prior(0);
    __syncthreads();                     // cross-thread visibility + uni reuse fence

    const float4* s4 = (const float4*)stage;
    #pragma unroll
    for (int k = 0; k < 8; k++)
        v[k] = s4[(cb + 8 * k) * 64 + r * 16 + p];

    // B: per-(c,r,p) row max -> pm
    #pragma unroll
    for (int k = 0; k < 8; k++) {
        float4 a = v[k];
        pm[r * 1040 + (cb + 8 * k) * 16 + p] =
            fmaxf(fmaxf(a.x, a.y), fmaxf(a.z, a.w));
    }
    __syncthreads();

    // ---- tile B chain (A's stores drain in background) ----
    rest(v, rbB);
}

extern "C" void kernel_launch(void* const* d_in, const int* in_sizes, int n_in,
                              void* d_out, int out_size) {
    const float* x    = (const float*)d_in[0];
    const float* fc_w = (const float*)d_in[1];
    const float* fc_b = (const float*)d_in[2];
    const float* c1w  = (const float*)d_in[3];
    const float* c1b  = (const float*)d_in[4];
    const float* c2w  = (const float*)d_in[5];
    const float* c2b  = (const float*)d_in[6];
    float* out = (float*)d_out;

    const int dyn = 16384 * sizeof(float);   // 64 KB tile-B stage
    cudaFuncSetAttribute(ciam_bg_kernel,
                         cudaFuncAttributeMaxDynamicSharedMemorySize, dyn);

    // 1024 blocks: 8 batches x 64 patch-rows x 2 tile-pairs; 2 tiles per block
    ciam_bg_kernel<<<1024, THREADS, dyn>>>(x, fc_w, fc_b, c1w, c1b, c2w, c2b, out);
}

// round 10
// speedup vs baseline: 1.0584x; 1.0584x over previous
#include <cuda_runtime.h>

// Problem constants (fixed by the dataset instance)
#define W_ 256
#define PLANE 65536
#define THREADS 256
// tile = 16 patches (64c x 4r x 64w) -> 2048 tiles, one block each

__device__ __forceinline__ float sigm(float x) {
    return 1.0f / (1.0f + __expf(-x));
}

__global__ __launch_bounds__(THREADS, 2)
void ciam_short_kernel(const float* __restrict__ x,
                       const float* __restrict__ fc_w,
                       const float* __restrict__ fc_b,
                       const float* __restrict__ c1w,
                       const float* __restrict__ c1b,
                       const float* __restrict__ c2w,
                       const float* __restrict__ c2b,
                       float* __restrict__ out)
{
    // ---- block / thread decomposition ----
    const int blk = blockIdx.x;          // 0..2047
    const int pwg = blk & 3;             // 16-patch group along W
    const int ph  = (blk >> 2) & 63;     // patch row
    const int b   = blk >> 8;            // batch

    const int t  = threadIdx.x;
    const int p  = t & 15;               // patch
    const int r  = (t >> 4) & 3;         // row within patch
    const int cb = t >> 6;               // channel base 0..3 (c = cb + 4k, k<16)
    const int rp = t & 63;               // (r, patch)

    // ---- shared memory (~26 KB) ----
    __shared__ float uni[4160];          // pm[4][1040] -> gsum[1024]+gmax[1024]+p2s/p2m[512]
    __shared__ float mxT[1024];          // channel maxes [c][p] (p contiguous)
    __shared__ float msm[1024];          // channel attention m[c][p]
    __shared__ float g1s[256];           // g1[(r,p)*4 + px]
    __shared__ float g2s[16];

    // ---- scalar weights ----
    const float c1w0 = __ldg(c1w), c1w1 = __ldg(c1w + 1), c1b0 = __ldg(c1b);
    const float c2w0 = __ldg(c2w), c2w1 = __ldg(c2w + 1), c2b0 = __ldg(c2b);

    // ---- load tile into registers (16 x float4 / thread, coalesced, streaming) ----
    const size_t plane = PLANE;
    const float* xb = x + (size_t)b * 64 * plane;
    float* ob = out + (size_t)b * 64 * plane;
    const int rowbase = (ph * 4 + r) * W_ + pwg * 64 + p * 4;

    float4 v[16];
    #pragma unroll
    for (int k = 0; k < 16; k++)
        v[k] = __ldcs((const float4*)(xb + (size_t)(cb + 4 * k) * plane + rowbase));

    // ---- phase 1: per-(c,r,p) row max -> pm (row stride 1040, conflict-free) ----
    float* pm = uni;                     // [r][c*16+p]
    #pragma unroll
    for (int k = 0; k < 16; k++) {
        float4 a = v[k];
        pm[r * 1040 + (cb + 4 * k) * 16 + p] =
            fmaxf(fmaxf(a.x, a.y), fmaxf(a.z, a.w));
    }
    __syncthreads();

    // ---- phase 2: reduce over r -> mxT (float4 form) ----
    {
        const int id4 = t * 4;           // 0..1020, covers c*16+p
        float4 a0 = *(const float4*)(pm + id4);
        float4 a1 = *(const float4*)(pm + 1040 + id4);
        float4 a2 = *(const float4*)(pm + 2080 + id4);
        float4 a3 = *(const float4*)(pm + 3120 + id4);
        float4 mr;
        mr.x = fmaxf(fmaxf(a0.x, a1.x), fmaxf(a2.x, a3.x));
        mr.y = fmaxf(fmaxf(a0.y, a1.y), fmaxf(a2.y, a3.y));
        mr.z = fmaxf(fmaxf(a0.z, a1.z), fmaxf(a2.z, a3.z));
        mr.w = fmaxf(fmaxf(a0.w, a1.w), fmaxf(a2.w, a3.w));
        *(float4*)(mxT + id4) = mr;
    }
    __syncthreads();

    // ---- phase 3: matvec m[c][p] = sigm(w[c].mx[:,p] + b[c]); 4 outputs/thread ----
    {
        const int c  = t >> 2;           // 0..63
        const int pq = (t & 3) * 4;      // 0,4,8,12
        float4 acc = make_float4(0.f, 0.f, 0.f, 0.f);
        #pragma unroll
        for (int kc = 0; kc < 16; kc++) {
            const float4 w4 = __ldg((const float4*)(fc_w + c * 64 + kc * 4));
            const float4 m0 = *(const float4*)(mxT + (kc * 4 + 0) * 16 + pq);
            const float4 m1 = *(const float4*)(mxT + (kc * 4 + 1) * 16 + pq);
            acc.x += w4.x * m0.x + w4.y * m1.x;
            acc.y += w4.x * m0.y + w4.y * m1.y;
            acc.z += w4.x * m0.z + w4.y * m1.z;
            acc.w += w4.x * m0.w + w4.y * m1.w;
            const float4 m2 = *(const float4*)(mxT + (kc * 4 + 2) * 16 + pq);
            const float4 m3 = *(const float4*)(mxT + (kc * 4 + 3) * 16 + pq);
            acc.x += w4.z * m2.x + w4.w * m3.x;
            acc.y += w4.z * m2.y + w4.w * m3.y;
            acc.z += w4.z * m2.z + w4.w * m3.z;
            acc.w += w4.z * m2.w + w4.w * m3.w;
        }
        const float bc = __ldg(fc_b + c);
        float4 mres;
        mres.x = sigm(acc.x + bc);
        mres.y = sigm(acc.y + bc);
        mres.z = sigm(acc.z + bc);
        mres.w = sigm(acc.w + bc);
        *(float4*)(msm + c * 16 + pq) = mres;
    }
    __syncthreads();

    // ---- phase 4: apply m; per-(patch,pixel) partials over this thread's 16 channels ----
    float4 ps  = make_float4(0.f, 0.f, 0.f, 0.f);
    float4 pmx = make_float4(-3.4e38f, -3.4e38f, -3.4e38f, -3.4e38f);
    #pragma unroll
    for (int k = 0; k < 16; k++) {
        const float m = msm[(cb + 4 * k) * 16 + p];
        v[k].x *= m; v[k].y *= m; v[k].z *= m; v[k].w *= m;
        ps.x += v[k].x; ps.y += v[k].y; ps.z += v[k].z; ps.w += v[k].w;
        pmx.x = fmaxf(pmx.x, v[k].x); pmx.y = fmaxf(pmx.y, v[k].y);
        pmx.z = fmaxf(pmx.z, v[k].z); pmx.w = fmaxf(pmx.w, v[k].w);
    }
    float* gsum = uni;                   // [cb][rp*4+px] : 1024 floats
    float* gmax = uni + 1024;
    *(float4*)(gsum + cb * 256 + rp * 4) = ps;
    *(float4*)(gmax + cb * 256 + rp * 4) = pmx;
    __syncthreads();

    // ---- phase 5: g1 per (patch,pixel) AND g2 partials (fused; no second tile pass) ----
    // S[px] = sum_c p1, M[px] = max_c p1 -> g1 = sigm(...);
    // g2 sum-part = g1*S, g2 max-part = g1*M  (g1 > 0 so max commutes)
    float* p2s = uni + 2048;             // 256 floats, indexed by t = (r,p,px)
    float* p2m = uni + 2304;
    {
        float s  = gsum[t] + gsum[256 + t] + gsum[512 + t] + gsum[768 + t];
        float mx = fmaxf(fmaxf(gmax[t], gmax[256 + t]), fmaxf(gmax[512 + t], gmax[768 + t]));
        const float g1 = sigm(c1w0 * (s * (1.0f / 64.0f)) + c1w1 * mx + c1b0);
        g1s[t] = g1;
        p2s[t] = g1 * s;
        p2m[t] = g1 * mx;
    }
    __syncthreads();

    // ---- phase 6: g2 per patch (16 (r,px) contributions each) ----
    if (t < 16) {
        float s = 0.f, mx = -3.4e38f;
        #pragma unroll
        for (int rr = 0; rr < 4; rr++) {
            #pragma unroll
            for (int px = 0; px < 4; px++) {
                const int id = rr * 64 + t * 4 + px;
                s += p2s[id];
                mx = fmaxf(mx, p2m[id]);
            }
        }
        g2s[t] = sigm(c2w0 * (s * (1.0f / 1024.0f)) + c2w1 * mx + c2b0);
    }
    __syncthreads();

    // ---- phase 7: y = v * g1 * g2, streamed store ----
    const float4 g1v = *(const float4*)(g1s + rp * 4);
    const float g2 = g2s[p];
    const float4 gg = make_float4(g1v.x * g2, g1v.y * g2, g1v.z * g2, g1v.w * g2);
    #pragma unroll
    for (int k = 0; k < 16; k++) {
        float4 a = v[k];
        a.x *= gg.x; a.y *= gg.y; a.z *= gg.z; a.w *= gg.w;
        __stcs((float4*)(ob + (size_t)(cb + 4 * k) * plane + rowbase), a);
    }
}

extern "C" void kernel_launch(void* const* d_in, const int* in_sizes, int n_in,
                              void* d_out, int out_size) {
    const float* x    = (const float*)d_in[0];
    const float* fc_w = (const float*)d_in[1];
    const float* fc_b = (const float*)d_in[2];
    const float* c1w  = (const float*)d_in[3];
    const float* c1b  = (const float*)d_in[4];
    const float* c2w  = (const float*)d_in[5];
    const float* c2b  = (const float*)d_in[6];
    float* out = (float*)d_out;

    // 2048 blocks: 8 batches x 64 patch-rows x 4 groups of 16 patches
    ciam_short_kernel<<<2048, THREADS>>>(x, fc_w, fc_b, c1w, c1b, c2w, c2b, out);
}

// round 11
// speedup vs baseline: 1.1716x; 1.1069x over previous
#include <cuda_runtime.h>

// Problem constants (fixed by the dataset instance)
#define W_ 256
#define PLANE 65536
#define THREADS 256
// tile = 16 patches (64c x 4r x 64w) -> 2048 tiles, one block each

__device__ __forceinline__ float sigm(float x) {
    return 1.0f / (1.0f + __expf(-x));
}

__global__ __launch_bounds__(THREADS, 2)
void ciam_r11_kernel(const float* __restrict__ x,
                     const float* __restrict__ fc_w,
                     const float* __restrict__ fc_b,
                     const float* __restrict__ c1w,
                     const float* __restrict__ c1b,
                     const float* __restrict__ c2w,
                     const float* __restrict__ c2b,
                     float* __restrict__ out)
{
    // ---- block / thread decomposition ----
    const int blk = blockIdx.x;          // 0..2047
    const int pwg = blk & 3;             // 16-patch group along W
    const int ph  = (blk >> 2) & 63;     // patch row
    const int b   = blk >> 8;            // batch

    const int t  = threadIdx.x;
    const int p  = t & 15;               // patch
    const int r  = (t >> 4) & 3;         // row within patch
    const int cb = t >> 6;               // channel base 0..3 (c = cb + 4k, k<16)
    const int rp = t & 63;               // (r, patch)

    // ---- shared memory (~43 KB, same layout family as R3) ----
    __shared__ float wS[64 * 68];        // fc_w rows, stride 68
    __shared__ float fcbS[64];
    __shared__ float mxT[1024];          // channel maxes [c][p] (p contiguous)
    __shared__ float msm[1024];          // channel attention m[c][p]
    __shared__ float g1s[256];           // g1[(r,p)*4 + px]
    __shared__ float g2s[16];
    __shared__ float uni[4160];          // pm[4][1040] -> gsum[1024]+gmax[1024]+p2s/p2m[512]

    // ---- scalar weights ----
    const float c1w0 = __ldg(c1w), c1w1 = __ldg(c1w + 1), c1b0 = __ldg(c1b);
    const float c2w0 = __ldg(c2w), c2w1 = __ldg(c2w + 1), c2b0 = __ldg(c2b);

    // ---- load tile into registers (16 x float4 / thread, coalesced) ----
    const size_t plane = PLANE;
    const float* xb = x + (size_t)b * 64 * plane;
    float* ob = out + (size_t)b * 64 * plane;
    const int rowbase = (ph * 4 + r) * W_ + pwg * 64 + p * 4;

    float4 v[16];
    #pragma unroll
    for (int k = 0; k < 16; k++)
        v[k] = *(const float4*)(xb + (size_t)(cb + 4 * k) * plane + rowbase);

    // ---- stage fc_w -> smem (stride 68), fc_b -> smem ----
    #pragma unroll
    for (int i = 0; i < 4; i++) {
        const int j  = t + 256 * i;      // float4 chunk id, 0..1023
        const int c  = j >> 4;
        const int k4 = j & 15;
        *(float4*)(wS + c * 68 + k4 * 4) = *(const float4*)(fc_w + c * 64 + k4 * 4);
    }
    if (t < 64) fcbS[t] = fc_b[t];

    // ---- phase 1: per-(c,r,p) row max -> pm (row stride 1040, conflict-free) ----
    float* pm = uni;                     // [r][c*16+p]
    #pragma unroll
    for (int k = 0; k < 16; k++) {
        float4 a = v[k];
        pm[r * 1040 + (cb + 4 * k) * 16 + p] =
            fmaxf(fmaxf(a.x, a.y), fmaxf(a.z, a.w));
    }
    __syncthreads();

    // ---- phase 2: reduce over r -> mxT (float4 form) ----
    {
        const int id4 = t * 4;           // 0..1020, covers c*16+p
        float4 a0 = *(const float4*)(pm + id4);
        float4 a1 = *(const float4*)(pm + 1040 + id4);
        float4 a2 = *(const float4*)(pm + 2080 + id4);
        float4 a3 = *(const float4*)(pm + 3120 + id4);
        float4 mr;
        mr.x = fmaxf(fmaxf(a0.x, a1.x), fmaxf(a2.x, a3.x));
        mr.y = fmaxf(fmaxf(a0.y, a1.y), fmaxf(a2.y, a3.y));
        mr.z = fmaxf(fmaxf(a0.z, a1.z), fmaxf(a2.z, a3.z));
        mr.w = fmaxf(fmaxf(a0.w, a1.w), fmaxf(a2.w, a3.w));
        *(float4*)(mxT + id4) = mr;
    }
    __syncthreads();

    // ---- phase 3: matvec m[c][p] = sigm(w[c].mx[:,p] + b[c]); 4 outputs/thread ----
    {
        const int c  = t >> 2;           // 0..63
        const int pq = (t & 3) * 4;      // 0,4,8,12
        float4 acc = make_float4(0.f, 0.f, 0.f, 0.f);
        #pragma unroll
        for (int kc = 0; kc < 16; kc++) {
            const float4 w4 = *(const float4*)(wS + c * 68 + kc * 4);
            const float4 m0 = *(const float4*)(mxT + (kc * 4 + 0) * 16 + pq);
            const float4 m1 = *(const float4*)(mxT + (kc * 4 + 1) * 16 + pq);
            acc.x += w4.x * m0.x + w4.y * m1.x;
            acc.y += w4.x * m0.y + w4.y * m1.y;
            acc.z += w4.x * m0.z + w4.y * m1.z;
            acc.w += w4.x * m0.w + w4.y * m1.w;
            const float4 m2 = *(const float4*)(mxT + (kc * 4 + 2) * 16 + pq);
            const float4 m3 = *(const float4*)(mxT + (kc * 4 + 3) * 16 + pq);
            acc.x += w4.z * m2.x + w4.w * m3.x;
            acc.y += w4.z * m2.y + w4.w * m3.y;
            acc.z += w4.z * m2.z + w4.w * m3.z;
            acc.w += w4.z * m2.w + w4.w * m3.w;
        }
        const float bc = fcbS[c];
        float4 mres;
        mres.x = sigm(acc.x + bc);
        mres.y = sigm(acc.y + bc);
        mres.z = sigm(acc.z + bc);
        mres.w = sigm(acc.w + bc);
        *(float4*)(msm + c * 16 + pq) = mres;
    }
    __syncthreads();

    // ---- phase 4: apply m; per-(patch,pixel) partials over this thread's 16 channels ----
    float4 ps  = make_float4(0.f, 0.f, 0.f, 0.f);
    float4 pmx = make_float4(-3.4e38f, -3.4e38f, -3.4e38f, -3.4e38f);
    #pragma unroll
    for (int k = 0; k < 16; k++) {
        const float m = msm[(cb + 4 * k) * 16 + p];
        v[k].x *= m; v[k].y *= m; v[k].z *= m; v[k].w *= m;
        ps.x += v[k].x; ps.y += v[k].y; ps.z += v[k].z; ps.w += v[k].w;
        pmx.x = fmaxf(pmx.x, v[k].x); pmx.y = fmaxf(pmx.y, v[k].y);
        pmx.z = fmaxf(pmx.z, v[k].z); pmx.w = fmaxf(pmx.w, v[k].w);
    }
    float* gsum = uni;                   // [cb][rp*4+px] : 1024 floats
    float* gmax = uni + 1024;
    *(float4*)(gsum + cb * 256 + rp * 4) = ps;
    *(float4*)(gmax + cb * 256 + rp * 4) = pmx;
    __syncthreads();

    // ---- phase 5: g1 per (patch,pixel) AND g2 partials (fused — no second tile pass) ----
    // S[px] = sum_c p1, M[px] = max_c p1 -> g1 = sigm(...);
    // g2 contributions: sum-part = g1*S, max-part = g1*M (g1 > 0 so max commutes)
    float* p2s = uni + 2048;             // 256 floats, indexed by t = (r,p,px)
    float* p2m = uni + 2304;
    {
        float s  = gsum[t] + gsum[256 + t] + gsum[512 + t] + gsum[768 + t];
        float mx = fmaxf(fmaxf(gmax[t], gmax[256 + t]), fmaxf(gmax[512 + t], gmax[768 + t]));
        const float g1 = sigm(c1w0 * (s * (1.0f / 64.0f)) + c1w1 * mx + c1b0);
        g1s[t] = g1;
        p2s[t] = g1 * s;
        p2m[t] = g1 * mx;
    }
    __syncthreads();

    // ---- phase 6: g2 per patch (16 (r,px) contributions each) ----
    if (t < 16) {
        float s = 0.f, mx = -3.4e38f;
        #pragma unroll
        for (int rr = 0; rr < 4; rr++) {
            #pragma unroll
            for (int px = 0; px < 4; px++) {
                const int id = rr * 64 + t * 4 + px;
                s += p2s[id];
                mx = fmaxf(mx, p2m[id]);
            }
        }
        g2s[t] = sigm(c2w0 * (s * (1.0f / 1024.0f)) + c2w1 * mx + c2b0);
    }
    __syncthreads();

    // ---- phase 7: y = v * (g1*g2), single store pass ----
    const float4 g1v = *(const float4*)(g1s + rp * 4);
    const float g2 = g2s[p];
    const float4 gg = make_float4(g1v.x * g2, g1v.y * g2, g1v.z * g2, g1v.w * g2);
    #pragma unroll
    for (int k = 0; k < 16; k++) {
        float4 a = v[k];
        a.x *= gg.x; a.y *= gg.y; a.z *= gg.z; a.w *= gg.w;
        *(float4*)(ob + (size_t)(cb + 4 * k) * plane + rowbase) = a;
    }
}

extern "C" void kernel_launch(void* const* d_in, const int* in_sizes, int n_in,
                              void* d_out, int out_size) {
    const float* x    = (const float*)d_in[0];
    const float* fc_w = (const float*)d_in[1];
    const float* fc_b = (const float*)d_in[2];
    const float* c1w  = (const float*)d_in[3];
    const float* c1b  = (const float*)d_in[4];
    const float* c2w  = (const float*)d_in[5];
    const float* c2b  = (const float*)d_in[6];
    float* out = (float*)d_out;

    // 2048 blocks: 8 batches x 64 patch-rows x 4 groups of 16 patches
    ciam_r11_kernel<<<2048, THREADS>>>(x, fc_w, fc_b, c1w, c1b, c2w, c2b, out);
}